// round 15
// baseline (speedup 1.0000x reference)
#include <cuda_runtime.h>
#include <cstdint>
#include <cstddef>

#define S     8192
#define LC    16
#define CH    64
#define HW    256
#define TAGS  50

typedef unsigned long long ull;

// ---------------- device scratch ----------------
__device__ __align__(256) float g_char_feat[S * CH];        // 2 MB
__device__ __align__(256) float g_gpre[(size_t)S * 4 * HW]; // 32 MB
__device__ __align__(256) float g_wh[(size_t)S * HW];       // 8 MB

// sync state, zeroed each launch via cudaMemsetAsync:
// [0] = gpre unit counter, [1] = tag chunk counter,
// [2..65]   = gpre chunk-done counts (64 chunks of 128 tokens, target 128)
// [66..129] = g_wh chunk-done counts (64 chunks of 128 tokens, target 256)
__device__ __align__(256) int g_sync[160];

// ---------------- helpers ----------------
__device__ __forceinline__ ull ffma2(ull a, ull b, ull c) {
    ull d;
    asm("fma.rn.f32x2 %0, %1, %2, %3;" : "=l"(d) : "l"(a), "l"(b), "l"(c));
    return d;
}
__device__ __forceinline__ ull packf2(float lo, float hi) {
    ull r;
    asm("mov.b64 %0, {%1, %2};" : "=l"(r) : "f"(lo), "f"(hi));
    return r;
}
__device__ __forceinline__ float f2sum(ull a) {
    float lo = __uint_as_float((unsigned)(a & 0xffffffffull));
    float hi = __uint_as_float((unsigned)(a >> 32));
    return lo + hi;
}
__device__ __forceinline__ float tanha(float x) {
    float y; asm("tanh.approx.f32 %0, %1;" : "=f"(y) : "f"(x)); return y;
}
__device__ __forceinline__ float sigm(float x) {
    return fmaf(0.5f, tanha(0.5f * x), 0.5f);
}
__device__ __forceinline__ uint32_t smem_u32(const void* p) {
    return (uint32_t)__cvta_generic_to_shared(p);
}
__device__ __forceinline__ uint32_t cluster_rank() {
    uint32_t r; asm("mov.u32 %0, %%cluster_ctarank;" : "=r"(r)); return r;
}
__device__ __forceinline__ uint32_t mapa_sh(uint32_t addr, uint32_t rank) {
    uint32_t r;
    asm("mapa.shared::cluster.u32 %0, %1, %2;" : "=r"(r) : "r"(addr), "r"(rank));
    return r;
}
__device__ __forceinline__ void mbar_init(uint32_t addr, uint32_t cnt) {
    asm volatile("mbarrier.init.shared.b64 [%0], %1;" :: "r"(addr), "r"(cnt) : "memory");
}
__device__ __forceinline__ void mbar_expect_tx(uint32_t addr, uint32_t bytes) {
    asm volatile("mbarrier.arrive.expect_tx.shared.b64 _, [%0], %1;"
                 :: "r"(addr), "r"(bytes) : "memory");
}
__device__ __forceinline__ void st_async_b32(uint32_t dst, float v, uint32_t mbar) {
    asm volatile("st.async.shared::cluster.mbarrier::complete_tx::bytes.b32 [%0], %1, [%2];"
                 :: "r"(dst), "r"(__float_as_uint(v)), "r"(mbar) : "memory");
}
__device__ __forceinline__ void mbar_wait_parity(uint32_t mbar, uint32_t parity) {
    asm volatile(
        "{\n\t.reg .pred P;\n"
        "W%=:\n\t"
        "mbarrier.try_wait.parity.acquire.cluster.shared::cta.b64 P, [%0], %1, 0x989680;\n\t"
        "@!P bra W%=;\n\t"
        "}" :: "r"(mbar), "r"(parity) : "memory");
}
__device__ __forceinline__ void cluster_sync_() {
    asm volatile("barrier.cluster.arrive.aligned;\n\tbarrier.cluster.wait.aligned;" ::: "memory");
}
__device__ __forceinline__ void named_bar(int id, int cnt) {
    asm volatile("bar.sync %0, %1;" :: "r"(id), "r"(cnt) : "memory");
}
__device__ __forceinline__ int ld_acq(const int* p) {
    int v;
    asm volatile("ld.acquire.gpu.global.s32 %0, [%1];" : "=r"(v) : "l"(p) : "memory");
    return v;
}
__device__ __forceinline__ void red_rel_add(int* p) {
    asm volatile("red.release.gpu.global.add.s32 [%0], 1;" :: "l"(p) : "memory");
}
__device__ __forceinline__ void wait_ge(const int* p, int tgt) {
    while (ld_acq(p) < tgt) { }
}
__device__ __forceinline__ void wait_ge_sleep(const int* p, int tgt) {
    while (ld_acq(p) < tgt) __nanosleep(1000);
}

// =====================================================================
// Kernel 1: char LSTM (round-13: length-sorted groups + named barriers)
// =====================================================================
#define CA_SW   (512 * 68)
#define CA_EMB  (128 * 64)
#define CA_HB   (32 * 64)
#define CA_SB   256
#define CHAR_SMEM_BYTES ((CA_SW + CA_EMB + CA_HB + CA_SB) * 4 + 512 * 4 + 64 * 4)

__global__ void __launch_bounds__(512, 1)
char_lstm_kernel(const int* __restrict__ ci_g, const int* __restrict__ clen,
                 const float* __restrict__ cemb_g,
                 const float* __restrict__ Wih, const float* __restrict__ Whh,
                 const float* __restrict__ bih, const float* __restrict__ bhh)
{
    extern __shared__ float smA[];
    float* sW    = smA;
    float* cemb  = sW + CA_SW;
    float* hbuf  = cemb + CA_EMB;
    float* sb    = hbuf + CA_HB;
    int*   scidx = (int*)(sb + CA_SB);
    int*   slens = scidx + 512;
    int*   ssort = slens + 32;

    const int tid = threadIdx.x;
    const int wbase = blockIdx.x * 32;

    for (int idx = tid; idx < 512 * 16; idx += 512) {
        int row = idx >> 4, k4 = idx & 15;
        const float* src = (row < 256) ? Wih + (size_t)row * 64 + k4 * 4
                                       : Whh + (size_t)(row - 256) * 64 + k4 * 4;
        *(float4*)&sW[row * 68 + k4 * 4] = *(const float4*)src;
    }
    for (int idx = tid; idx < 128 * 16; idx += 512) {
        int row = idx >> 4, k4 = idx & 15;
        *(float4*)&cemb[row * 64 + k4 * 4] = *(const float4*)(cemb_g + (size_t)row * 64 + k4 * 4);
    }
    if (tid < 256) sb[tid] = bih[tid] + bhh[tid];
    scidx[tid] = ci_g[(size_t)wbase * 16 + tid];
    if (tid < 32) slens[tid] = clen[wbase + tid];
    for (int idx = tid; idx < CA_HB; idx += 512) hbuf[idx] = 0.f;
    __syncthreads();

    if (tid < 32) {
        int ml = slens[tid];
        int rank = 0;
        #pragma unroll
        for (int j = 0; j < 32; j++) {
            int lj = slens[j];
            rank += (lj < ml || (lj == ml && j < tid)) ? 1 : 0;
        }
        ssort[rank] = tid;
    }
    __syncthreads();

    const int rt = tid & 63, wt = tid >> 6, w0 = wt * 4;
    const int perm_tab[8] = {0, 1, 3, 2, 4, 5, 7, 6};
    const int q0 = perm_tab[wt] * 4;

    int wloc[4], len[4]; float cc[4];
    #pragma unroll
    for (int i = 0; i < 4; i++) {
        wloc[i] = ssort[q0 + i];
        len[i]  = slens[wloc[i]];
        cc[i]   = 0.f;
    }
    const int tmax = len[3];
    const int barid = wt + 1;

    for (int t = 0; t < tmax; t++) {
        int ci[4];
        #pragma unroll
        for (int i = 0; i < 4; i++) ci[i] = scidx[wloc[i] * 16 + t];

        ull acc[4][4];
        #pragma unroll
        for (int i = 0; i < 4; i++)
            #pragma unroll
            for (int q = 0; q < 4; q++) acc[i][q] = 0ull;

        #pragma unroll
        for (int k4 = 0; k4 < 16; k4++) {
            ulonglong2 wv[4];
            #pragma unroll
            for (int q = 0; q < 4; q++)
                wv[q] = *(const ulonglong2*)&sW[(q * 64 + rt) * 68 + k4 * 4];
            #pragma unroll
            for (int i = 0; i < 4; i++) {
                ulonglong2 xv = *(const ulonglong2*)&cemb[ci[i] * 64 + k4 * 4];
                #pragma unroll
                for (int q = 0; q < 4; q++) {
                    acc[i][q] = ffma2(xv.x, wv[q].x, acc[i][q]);
                    acc[i][q] = ffma2(xv.y, wv[q].y, acc[i][q]);
                }
            }
        }
        #pragma unroll
        for (int k4 = 0; k4 < 16; k4++) {
            ulonglong2 wv[4];
            #pragma unroll
            for (int q = 0; q < 4; q++)
                wv[q] = *(const ulonglong2*)&sW[(256 + q * 64 + rt) * 68 + k4 * 4];
            #pragma unroll
            for (int i = 0; i < 4; i++) {
                ulonglong2 hv = *(const ulonglong2*)&hbuf[(w0 + i) * 64 + k4 * 4];
                #pragma unroll
                for (int q = 0; q < 4; q++) {
                    acc[i][q] = ffma2(hv.x, wv[q].x, acc[i][q]);
                    acc[i][q] = ffma2(hv.y, wv[q].y, acc[i][q]);
                }
            }
        }
        named_bar(barid, 64);

        float bI = sb[rt], bF = sb[64 + rt], bG = sb[128 + rt], bO = sb[192 + rt];
        #pragma unroll
        for (int i = 0; i < 4; i++) {
            float gi = f2sum(acc[i][0]) + bI;
            float gf = f2sum(acc[i][1]) + bF;
            float gG = f2sum(acc[i][2]) + bG;
            float go = f2sum(acc[i][3]) + bO;
            cc[i] = fmaf(sigm(gf), cc[i], sigm(gi) * tanha(gG));
            float h = sigm(go) * tanha(cc[i]);
            hbuf[(w0 + i) * 64 + rt] = h;
            if (t == len[i] - 1)
                g_char_feat[(size_t)(wbase + wloc[i]) * 64 + rt] = h;
        }
        named_bar(barid, 64);
    }
}

// =====================================================================
// Mega kernel: 17 clusters x 8 CTAs.
//   cluster 0: word recurrence; gpre-ready acquire polls every 64 pairs;
//     g_wh chunk completion via per-writer red.release (no fence/extra bar).
//   clusters 1..16: work-steal gpre units, then tag chunks.
// =====================================================================
#define BP 196
#define TAG_SW     (256 * 64)
#define TAG_DYN_F  (TAG_SW + 64)
#define MEGA_DYN_BYTES (TAG_DYN_F * 4)

#define GFOLD(G_) ((oct == 0) ? (ull)__float_as_uint(G_) : 0ull)

#define WSTEP(BARADDR, PAR, G0_, G1_, G2_, G3_, SH_OFF, ST_DOFF, ST_BOFF, TIDX, DO_EXPECT, DO_STORE, HLR_, HLW_, DO_BAR, SIGP) \
    do {                                                                                              \
        float4 hl_ = *(const float4*)&hloc[HLR_][oct * 4];                                            \
        ull hvA_ = packf2(hl_.x, hl_.y), hvB_ = packf2(hl_.z, hl_.w);                                 \
        ull a0_ = ffma2(hvA_, rwr0.x, GFOLD(G0_)); a0_ = ffma2(hvB_, rwr0.y, a0_);                    \
        ull a1_ = ffma2(hvA_, rwr1.x, GFOLD(G1_)); a1_ = ffma2(hvB_, rwr1.y, a1_);                    \
        ull a2_ = ffma2(hvA_, rwr2.x, GFOLD(G2_)); a2_ = ffma2(hvB_, rwr2.y, a2_);                    \
        ull a3_ = ffma2(hvA_, rwr3.x, GFOLD(G3_)); a3_ = ffma2(hvB_, rwr3.y, a3_);                    \
        mbar_wait_parity((BARADDR), (PAR));                                                           \
        if ((DO_EXPECT) && tid == 0) mbar_expect_tx((BARADDR), 1024);                                 \
        const char* hbb_ = (const char*)sh + (SH_OFF);                                                \
        _Pragma("unroll")                                                                             \
        for (int i_ = 0; i_ < 7; i_++) {                                                              \
            ulonglong2 hv_ = *(const ulonglong2*)(hbb_ + offs[i_]);                                   \
            a0_ = ffma2(hv_.x, rw0[i_].x, a0_); a0_ = ffma2(hv_.y, rw0[i_].y, a0_);                   \
            a1_ = ffma2(hv_.x, rw1[i_].x, a1_); a1_ = ffma2(hv_.y, rw1[i_].y, a1_);                   \
            a2_ = ffma2(hv_.x, rw2[i_].x, a2_); a2_ = ffma2(hv_.y, rw2[i_].y, a2_);                   \
            a3_ = ffma2(hv_.x, rw3[i_].x, a3_); a3_ = ffma2(hv_.y, rw3[i_].y, a3_);                   \
        }                                                                                             \
        float s0_ = f2sum(a0_), s1_ = f2sum(a1_), s2_ = f2sum(a2_), s3_ = f2sum(a3_);                 \
        _Pragma("unroll")                                                                             \
        for (int off_ = 1; off_ <= 4; off_ <<= 1) {                                                   \
            s0_ += __shfl_xor_sync(0xFFFFFFFFu, s0_, off_);                                           \
            s1_ += __shfl_xor_sync(0xFFFFFFFFu, s1_, off_);                                           \
            s2_ += __shfl_xor_sync(0xFFFFFFFFu, s2_, off_);                                           \
            s3_ += __shfl_xor_sync(0xFFFFFFFFu, s3_, off_);                                           \
        }                                                                                             \
        c = fmaf(sigm(s1_), c, sigm(s0_) * tanha(s2_));                                               \
        float h_ = sigm(s3_) * tanha(c);                                                              \
        if (DO_STORE)                                                                                 \
            st_async_b32(dst_my - (ST_DOFF), h_, bar_my - (ST_BOFF));                                 \
        if (is_writer) {                                                                              \
            gwp[(size_t)(TIDX) * HW] = h_;                                                            \
            int* sp_ = (SIGP);                                                                        \
            if (sp_) red_rel_add(sp_);                                                                \
        }                                                                                             \
        if (DO_BAR) {                                                                                 \
            if (is_writer) hloc[HLW_][jj] = h_;                                                       \
            __syncthreads();                                                                          \
        }                                                                                             \
    } while (0)

__global__ void __launch_bounds__(256, 1) __cluster_dims__(8, 1, 1)
mega_kernel(const float* __restrict__ Whh,
            const int* __restrict__ widx, const float* __restrict__ wemb,
            const float* __restrict__ Wih,
            const float* __restrict__ bih, const float* __restrict__ bhh,
            const float* __restrict__ tagW, const float* __restrict__ tagb,
            float* __restrict__ out)
{
    extern __shared__ float dynsm[];
    __shared__ float sh[2][256];
    __shared__ float hloc[2][32];
    __shared__ __align__(8) unsigned long long bar2[2];
    __shared__ int s_u;

    const int tid = threadIdx.x;

    if (blockIdx.x < 8) {
        // ================= WORD RECURRENCE (cluster 0) =================
        const int jj  = tid >> 3;
        const int oct = tid & 7;
        const uint32_t rank = cluster_rank();
        const int uglob = (int)rank * 32 + jj;

        ulonglong2 rw0[7], rw1[7], rw2[7], rw3[7];
        ulonglong2 rwr0, rwr1, rwr2, rwr3;
        uint32_t offs[7];
        {
            const float* base = Whh + (size_t)uglob * 256 + oct * 4;
            rwr0 = *(const ulonglong2*)(base + 0 * 65536 + (int)rank * 32);
            rwr1 = *(const ulonglong2*)(base + 1 * 65536 + (int)rank * 32);
            rwr2 = *(const ulonglong2*)(base + 2 * 65536 + (int)rank * 32);
            rwr3 = *(const ulonglong2*)(base + 3 * 65536 + (int)rank * 32);
            int j = 0;
            for (int mm = 0; mm < 8; mm++) {
                if (mm == (int)rank) continue;
                rw0[j] = *(const ulonglong2*)(base + 0 * 65536 + mm * 32);
                rw1[j] = *(const ulonglong2*)(base + 1 * 65536 + mm * 32);
                rw2[j] = *(const ulonglong2*)(base + 2 * 65536 + mm * 32);
                rw3[j] = *(const ulonglong2*)(base + 3 * 65536 + mm * 32);
                offs[j] = (uint32_t)(oct + mm * 8) * 16u;
                j++;
            }
        }

        sh[0][tid] = 0.f;
        sh[1][tid] = 0.f;
        if (tid < 64) hloc[tid >> 5][tid & 31] = 0.f;
        const uint32_t locb0 = smem_u32(&bar2[0]);
        const uint32_t locb1 = smem_u32(&bar2[1]);
        if (tid == 0) {
            mbar_init(locb0, 1);
            mbar_init(locb1, 1);
            mbar_expect_tx(locb0, 1024);
            mbar_expect_tx(locb1, 1024);
        }
        __syncthreads();
        cluster_sync_();

        const uint32_t dst_my = mapa_sh(smem_u32(&sh[1][uglob]), (uint32_t)oct);
        const uint32_t bar_my = mapa_sh(locb1, (uint32_t)oct);

        float c = 0.f;
        const bool is_writer = (oct == 0);
        float* const gwp = g_wh + uglob;

        // wait for gpre chunk 0 (tokens 0..127)
        wait_ge(&g_sync[2], 128);

        // ---------- t = 0 ----------
        {
            const float* gpp0 = g_gpre + uglob;
            float gp0 = gpp0[0], gp2 = gpp0[512], gp3 = gpp0[768];
            c = sigm(gp0) * tanha(gp2);
            float h = sigm(gp3) * tanha(c);
            st_async_b32(dst_my, h, bar_my);
            if (is_writer) { gwp[0] = h; hloc[0][jj] = h; }
            __syncthreads();
        }

        // ---------- interior pairs: m = 0..4093 covers t = 1..8188 ----------
        const float* gpp = g_gpre + 1024 + uglob;
        float A0, A1, A2, A3;
        float B0, B1, B2, B3;
        A0 = gpp[0];    A1 = gpp[256];  A2 = gpp[512];  A3 = gpp[768];
        B0 = gpp[1024]; B1 = gpp[1280]; B2 = gpp[1536]; B3 = gpp[1792];

        for (int m = 0; m < 4094; m++) {
            if ((m & 63) == 0) {
                int cc_ = (m >> 6) + 1;
                if (cc_ < 64) wait_ge(&g_sync[2 + cc_], 128);
            }
            const float* np = gpp + 2048;
            float N0 = np[0],    N1 = np[256],  N2 = np[512],  N3 = np[768];
            float M0 = np[1024], M1 = np[1280], M2 = np[1536], M3 = np[1792];
            const uint32_t ph = (uint32_t)m & 1u;
            // chunk signal on pair end: tokens <= 2m+2 complete chunk m>>6 when (m&63)==63
            int* sigp = ((m & 63) == 63) ? &g_sync[66 + (m >> 6)] : (int*)0;

            WSTEP(locb1, ph, A0, A1, A2, A3, 1024u, 1024u, 8u, 2 * m + 1, 1, 1, 0, 1, 1, (int*)0);
            WSTEP(locb0, ph, B0, B1, B2, B3, 0u, 0u, 0u, 2 * m + 2, 1, 1, 1, 0, 1, sigp);

            A0 = N0; A1 = N1; A2 = N2; A3 = N3;
            B0 = M0; B1 = M1; B2 = M2; B3 = M3;
            gpp += 2048;
        }

        // ---------- tail: t = 8189, 8190, 8191 ----------
        {
            const float* fp = gpp + 2048;
            float F0 = fp[0], F1 = fp[256], F2 = fp[512], F3 = fp[768];
            WSTEP(locb1, 0u, A0, A1, A2, A3, 1024u, 1024u, 8u, 8189, 1, 1, 0, 1, 1, (int*)0);
            WSTEP(locb0, 0u, B0, B1, B2, B3, 0u, 0u, 0u, 8190, 1, 1, 1, 0, 1, (int*)0);
            WSTEP(locb1, 1u, F0, F1, F2, F3, 1024u, 0u, 0u, 8191, 0, 0, 0, 1, 0, &g_sync[66 + 63]);
        }
        return;
    }

    // ================= WORKERS (clusters 1..16) =================
    // ---- phase 1: gpre producers (work-steal 8192 units of 16t x 64G) ----
    {
        float* sx = dynsm;            // [16][196]
        float* sw = dynsm + 16 * BP;  // [64][196]
        for (;;) {
            if (tid == 0) s_u = atomicAdd(&g_sync[0], 1);
            __syncthreads();
            const int u = s_u;
            if (u >= 8192) break;
            const int t0 = (u >> 4) * 16;
            const int G0 = (u & 15) * 64;

            for (int i = tid; i < 16 * 48; i += 256) {
                int tt = i / 48, k4 = i % 48;
                float4 v = (k4 < 32)
                    ? *(const float4*)(wemb + (size_t)widx[t0 + tt] * 128 + k4 * 4)
                    : *(const float4*)(g_char_feat + (size_t)(t0 + tt) * 64 + (k4 - 32) * 4);
                *(float4*)&sx[tt * BP + k4 * 4] = v;
            }
            for (int i = tid; i < 64 * 48; i += 256) {
                int r = i / 48, k4 = i % 48;
                *(float4*)&sw[r * BP + k4 * 4] = *(const float4*)(Wih + (size_t)(G0 + r) * 192 + k4 * 4);
            }
            __syncthreads();

            const int g = tid & 63, tq = tid >> 6;
            ull ax[4], ay[4];
            #pragma unroll
            for (int i = 0; i < 4; i++) { ax[i] = 0ull; ay[i] = 0ull; }

            #pragma unroll 4
            for (int k4 = 0; k4 < 48; k4++) {
                ulonglong2 wv = *(const ulonglong2*)&sw[g * BP + k4 * 4];
                #pragma unroll
                for (int it = 0; it < 4; it++) {
                    ulonglong2 xv = *(const ulonglong2*)&sx[(tq * 4 + it) * BP + k4 * 4];
                    ax[it] = ffma2(xv.x, wv.x, ax[it]);
                    ay[it] = ffma2(xv.y, wv.y, ay[it]);
                }
            }
            float b = bih[G0 + g] + bhh[G0 + g];
            #pragma unroll
            for (int it = 0; it < 4; it++)
                g_gpre[(size_t)(t0 + tq * 4 + it) * 1024 + G0 + g] = f2sum(ax[it]) + f2sum(ay[it]) + b;

            __threadfence();
            __syncthreads();
            if (tid == 0) atomicAdd(&g_sync[2 + (t0 >> 7)], 1);
        }
    }

    // ---- phase 2: tag consumers (work-steal 64 chunks of 128 tokens) ----
    {
        float* tsw = dynsm;            // [256][64] transposed tagW
        float* tsb = dynsm + TAG_SW;   // [64]
        __syncthreads();
        for (int i = tid; i < TAG_SW; i += 256) tsw[i] = 0.f;
        if (tid < 64) tsb[tid] = (tid < TAGS) ? tagb[tid] : 0.f;
        __syncthreads();
        for (int i = tid; i < TAGS * 256; i += 256) {
            int tg = i >> 8, k = i & 255;
            tsw[k * 64 + tg] = tagW[i];
        }
        __syncthreads();

        const int lane = tid & 31, warp = tid >> 5;
        const bool v1 = (32 + lane) < TAGS;

        for (;;) {
            if (tid == 0) s_u = atomicAdd(&g_sync[1], 1);
            __syncthreads();
            const int ck = s_u;
            if (ck >= 64) break;
            wait_ge_sleep(&g_sync[66 + ck], 256);   // 8 CTAs x 32 writers

            #pragma unroll 1
            for (int it = 0; it < 16; it++) {
                const int token = ck * 128 + it * 8 + warp;
                const float4* hp4 = (const float4*)(g_wh + (size_t)token * 256);

                float a0 = 0.f, a1 = 0.f;
                #pragma unroll 8
                for (int k4 = 0; k4 < 64; k4++) {
                    float4 h = hp4[k4];
                    const float* p = tsw + k4 * 256 + lane;
                    a0 = fmaf(h.x, p[0],   a0);  a1 = fmaf(h.x, p[32],  a1);
                    a0 = fmaf(h.y, p[64],  a0);  a1 = fmaf(h.y, p[96],  a1);
                    a0 = fmaf(h.z, p[128], a0);  a1 = fmaf(h.z, p[160], a1);
                    a0 = fmaf(h.w, p[192], a0);  a1 = fmaf(h.w, p[224], a1);
                }
                a0 += tsb[lane];
                a1 += tsb[32 + lane];

                float mx = fmaxf(a0, v1 ? a1 : -3.4e38f);
                #pragma unroll
                for (int off = 16; off; off >>= 1)
                    mx = fmaxf(mx, __shfl_xor_sync(0xFFFFFFFFu, mx, off));
                float e = __expf(a0 - mx) + (v1 ? __expf(a1 - mx) : 0.f);
                #pragma unroll
                for (int off = 16; off; off >>= 1)
                    e += __shfl_xor_sync(0xFFFFFFFFu, e, off);
                float ls = __logf(e);

                out[(size_t)token * TAGS + lane] = a0 - mx - ls;
                if (v1) out[(size_t)token * TAGS + 32 + lane] = a1 - mx - ls;
            }
        }
    }
}

// =====================================================================
extern "C" void kernel_launch(void* const* d_in, const int* in_sizes, int n_in,
                              void* d_out, int out_size)
{
    const int*   word_idxs = (const int*)d_in[0];
    const int*   char_idxs = (const int*)d_in[1];
    const int*   char_lens = (const int*)d_in[2];
    const float* char_emb  = (const float*)d_in[3];
    const float* char_Wih  = (const float*)d_in[4];
    const float* char_Whh  = (const float*)d_in[5];
    const float* char_bih  = (const float*)d_in[6];
    const float* char_bhh  = (const float*)d_in[7];
    const float* word_emb  = (const float*)d_in[8];
    const float* word_Wih  = (const float*)d_in[9];
    const float* word_Whh  = (const float*)d_in[10];
    const float* word_bih  = (const float*)d_in[11];
    const float* word_bhh  = (const float*)d_in[12];
    const float* tag_W     = (const float*)d_in[13];
    const float* tag_b     = (const float*)d_in[14];
    float* out = (float*)d_out;

    void* sync_addr = nullptr;
    cudaGetSymbolAddress(&sync_addr, g_sync);
    cudaMemsetAsync(sync_addr, 0, sizeof(int) * 160);

    cudaFuncSetAttribute(char_lstm_kernel,
                         cudaFuncAttributeMaxDynamicSharedMemorySize, CHAR_SMEM_BYTES);
    cudaFuncSetAttribute(mega_kernel,
                         cudaFuncAttributeMaxDynamicSharedMemorySize, MEGA_DYN_BYTES);

    char_lstm_kernel<<<256, 512, CHAR_SMEM_BYTES>>>(
        char_idxs, char_lens, char_emb, char_Wih, char_Whh, char_bih, char_bhh);

    mega_kernel<<<136, 256, MEGA_DYN_BYTES>>>(
        word_Whh, word_idxs, word_emb, word_Wih, word_bih, word_bhh,
        tag_W, tag_b, out);
}

// round 16
// speedup vs baseline: 1.2137x; 1.2137x over previous
#include <cuda_runtime.h>
#include <cstdint>
#include <cstddef>

#define S     8192
#define LC    16
#define CH    64
#define HW    256
#define TAGS  50

typedef unsigned long long ull;

// ---------------- device scratch ----------------
__device__ __align__(256) float g_char_feat[S * CH];        // 2 MB
__device__ __align__(256) float g_gpre[(size_t)S * 4 * HW]; // 32 MB
__device__ __align__(256) float g_wh[(size_t)S * HW];       // 8 MB

// sync state, zeroed each launch via cudaMemsetAsync:
// [0] = gpre unit counter, [1] = tag chunk counter,
// [2..65]   = gpre chunk-done counts (64 chunks of 128 tokens, target 128)
// [66..129] = g_wh chunk-done counts (64 chunks of 128 tokens, target 8)
__device__ __align__(256) int g_sync[160];

// ---------------- helpers ----------------
__device__ __forceinline__ ull ffma2(ull a, ull b, ull c) {
    ull d;
    asm("fma.rn.f32x2 %0, %1, %2, %3;" : "=l"(d) : "l"(a), "l"(b), "l"(c));
    return d;
}
__device__ __forceinline__ ull packf2(float lo, float hi) {
    ull r;
    asm("mov.b64 %0, {%1, %2};" : "=l"(r) : "f"(lo), "f"(hi));
    return r;
}
__device__ __forceinline__ float f2sum(ull a) {
    float lo = __uint_as_float((unsigned)(a & 0xffffffffull));
    float hi = __uint_as_float((unsigned)(a >> 32));
    return lo + hi;
}
__device__ __forceinline__ float tanha(float x) {
    float y; asm("tanh.approx.f32 %0, %1;" : "=f"(y) : "f"(x)); return y;
}
__device__ __forceinline__ float sigm(float x) {
    return fmaf(0.5f, tanha(0.5f * x), 0.5f);
}
__device__ __forceinline__ uint32_t smem_u32(const void* p) {
    return (uint32_t)__cvta_generic_to_shared(p);
}
__device__ __forceinline__ uint32_t cluster_rank() {
    uint32_t r; asm("mov.u32 %0, %%cluster_ctarank;" : "=r"(r)); return r;
}
__device__ __forceinline__ uint32_t mapa_sh(uint32_t addr, uint32_t rank) {
    uint32_t r;
    asm("mapa.shared::cluster.u32 %0, %1, %2;" : "=r"(r) : "r"(addr), "r"(rank));
    return r;
}
__device__ __forceinline__ void mbar_init(uint32_t addr, uint32_t cnt) {
    asm volatile("mbarrier.init.shared.b64 [%0], %1;" :: "r"(addr), "r"(cnt) : "memory");
}
__device__ __forceinline__ void mbar_expect_tx(uint32_t addr, uint32_t bytes) {
    asm volatile("mbarrier.arrive.expect_tx.shared.b64 _, [%0], %1;"
                 :: "r"(addr), "r"(bytes) : "memory");
}
__device__ __forceinline__ void st_async_b32(uint32_t dst, float v, uint32_t mbar) {
    asm volatile("st.async.shared::cluster.mbarrier::complete_tx::bytes.b32 [%0], %1, [%2];"
                 :: "r"(dst), "r"(__float_as_uint(v)), "r"(mbar) : "memory");
}
__device__ __forceinline__ void mbar_wait_parity(uint32_t mbar, uint32_t parity) {
    asm volatile(
        "{\n\t.reg .pred P;\n"
        "W%=:\n\t"
        "mbarrier.try_wait.parity.acquire.cluster.shared::cta.b64 P, [%0], %1, 0x989680;\n\t"
        "@!P bra W%=;\n\t"
        "}" :: "r"(mbar), "r"(parity) : "memory");
}
__device__ __forceinline__ void cluster_sync_() {
    asm volatile("barrier.cluster.arrive.aligned;\n\tbarrier.cluster.wait.aligned;" ::: "memory");
}
__device__ __forceinline__ void named_bar(int id, int cnt) {
    asm volatile("bar.sync %0, %1;" :: "r"(id), "r"(cnt) : "memory");
}
__device__ __forceinline__ int ld_acq(const int* p) {
    int v;
    asm volatile("ld.acquire.gpu.global.s32 %0, [%1];" : "=r"(v) : "l"(p) : "memory");
    return v;
}
__device__ __forceinline__ void wait_ge(const int* p, int tgt) {
    while (ld_acq(p) < tgt) { }
}
__device__ __forceinline__ void wait_ge_sleep(const int* p, int tgt) {
    while (ld_acq(p) < tgt) __nanosleep(1000);
}

// =====================================================================
// Kernel 1: char LSTM (round-13: length-sorted groups + named barriers)
// =====================================================================
#define CA_SW   (512 * 68)
#define CA_EMB  (128 * 64)
#define CA_HB   (32 * 64)
#define CA_SB   256
#define CHAR_SMEM_BYTES ((CA_SW + CA_EMB + CA_HB + CA_SB) * 4 + 512 * 4 + 64 * 4)

__global__ void __launch_bounds__(512, 1)
char_lstm_kernel(const int* __restrict__ ci_g, const int* __restrict__ clen,
                 const float* __restrict__ cemb_g,
                 const float* __restrict__ Wih, const float* __restrict__ Whh,
                 const float* __restrict__ bih, const float* __restrict__ bhh)
{
    extern __shared__ float smA[];
    float* sW    = smA;
    float* cemb  = sW + CA_SW;
    float* hbuf  = cemb + CA_EMB;
    float* sb    = hbuf + CA_HB;
    int*   scidx = (int*)(sb + CA_SB);
    int*   slens = scidx + 512;
    int*   ssort = slens + 32;

    const int tid = threadIdx.x;
    const int wbase = blockIdx.x * 32;

    for (int idx = tid; idx < 512 * 16; idx += 512) {
        int row = idx >> 4, k4 = idx & 15;
        const float* src = (row < 256) ? Wih + (size_t)row * 64 + k4 * 4
                                       : Whh + (size_t)(row - 256) * 64 + k4 * 4;
        *(float4*)&sW[row * 68 + k4 * 4] = *(const float4*)src;
    }
    for (int idx = tid; idx < 128 * 16; idx += 512) {
        int row = idx >> 4, k4 = idx & 15;
        *(float4*)&cemb[row * 64 + k4 * 4] = *(const float4*)(cemb_g + (size_t)row * 64 + k4 * 4);
    }
    if (tid < 256) sb[tid] = bih[tid] + bhh[tid];
    scidx[tid] = ci_g[(size_t)wbase * 16 + tid];
    if (tid < 32) slens[tid] = clen[wbase + tid];
    for (int idx = tid; idx < CA_HB; idx += 512) hbuf[idx] = 0.f;
    __syncthreads();

    if (tid < 32) {
        int ml = slens[tid];
        int rank = 0;
        #pragma unroll
        for (int j = 0; j < 32; j++) {
            int lj = slens[j];
            rank += (lj < ml || (lj == ml && j < tid)) ? 1 : 0;
        }
        ssort[rank] = tid;
    }
    __syncthreads();

    const int rt = tid & 63, wt = tid >> 6, w0 = wt * 4;
    const int perm_tab[8] = {0, 1, 3, 2, 4, 5, 7, 6};
    const int q0 = perm_tab[wt] * 4;

    int wloc[4], len[4]; float cc[4];
    #pragma unroll
    for (int i = 0; i < 4; i++) {
        wloc[i] = ssort[q0 + i];
        len[i]  = slens[wloc[i]];
        cc[i]   = 0.f;
    }
    const int tmax = len[3];
    const int barid = wt + 1;

    for (int t = 0; t < tmax; t++) {
        int ci[4];
        #pragma unroll
        for (int i = 0; i < 4; i++) ci[i] = scidx[wloc[i] * 16 + t];

        ull acc[4][4];
        #pragma unroll
        for (int i = 0; i < 4; i++)
            #pragma unroll
            for (int q = 0; q < 4; q++) acc[i][q] = 0ull;

        #pragma unroll
        for (int k4 = 0; k4 < 16; k4++) {
            ulonglong2 wv[4];
            #pragma unroll
            for (int q = 0; q < 4; q++)
                wv[q] = *(const ulonglong2*)&sW[(q * 64 + rt) * 68 + k4 * 4];
            #pragma unroll
            for (int i = 0; i < 4; i++) {
                ulonglong2 xv = *(const ulonglong2*)&cemb[ci[i] * 64 + k4 * 4];
                #pragma unroll
                for (int q = 0; q < 4; q++) {
                    acc[i][q] = ffma2(xv.x, wv[q].x, acc[i][q]);
                    acc[i][q] = ffma2(xv.y, wv[q].y, acc[i][q]);
                }
            }
        }
        #pragma unroll
        for (int k4 = 0; k4 < 16; k4++) {
            ulonglong2 wv[4];
            #pragma unroll
            for (int q = 0; q < 4; q++)
                wv[q] = *(const ulonglong2*)&sW[(256 + q * 64 + rt) * 68 + k4 * 4];
            #pragma unroll
            for (int i = 0; i < 4; i++) {
                ulonglong2 hv = *(const ulonglong2*)&hbuf[(w0 + i) * 64 + k4 * 4];
                #pragma unroll
                for (int q = 0; q < 4; q++) {
                    acc[i][q] = ffma2(hv.x, wv[q].x, acc[i][q]);
                    acc[i][q] = ffma2(hv.y, wv[q].y, acc[i][q]);
                }
            }
        }
        named_bar(barid, 64);

        float bI = sb[rt], bF = sb[64 + rt], bG = sb[128 + rt], bO = sb[192 + rt];
        #pragma unroll
        for (int i = 0; i < 4; i++) {
            float gi = f2sum(acc[i][0]) + bI;
            float gf = f2sum(acc[i][1]) + bF;
            float gG = f2sum(acc[i][2]) + bG;
            float go = f2sum(acc[i][3]) + bO;
            cc[i] = fmaf(sigm(gf), cc[i], sigm(gi) * tanha(gG));
            float h = sigm(go) * tanha(cc[i]);
            hbuf[(w0 + i) * 64 + rt] = h;
            if (t == len[i] - 1)
                g_char_feat[(size_t)(wbase + wloc[i]) * 64 + rt] = h;
        }
        named_bar(barid, 64);
    }
}

// =====================================================================
// Mega kernel: 17 clusters x 8 CTAs.
//   cluster 0: word recurrence, CHUNK-OUTER / BRANCH-FREE-INNER:
//     all polls and signals live at chunk boundaries (outside the
//     branch-free 64-pair inner loop — round-8 lesson preserved).
//   clusters 1..16: work-steal gpre units, then tag chunks (round-14).
// =====================================================================
#define BP 196
#define TAG_SW     (256 * 64)
#define TAG_DYN_F  (TAG_SW + 64)
#define MEGA_DYN_BYTES (TAG_DYN_F * 4)

#define GFOLD(G_) ((oct == 0) ? (ull)__float_as_uint(G_) : 0ull)

#define WSTEP(BARADDR, PAR, G0_, G1_, G2_, G3_, SH_OFF, ST_DOFF, ST_BOFF, TIDX, DO_EXPECT, DO_STORE, HLR_, HLW_, DO_BAR) \
    do {                                                                                              \
        float4 hl_ = *(const float4*)&hloc[HLR_][oct * 4];                                            \
        ull hvA_ = packf2(hl_.x, hl_.y), hvB_ = packf2(hl_.z, hl_.w);                                 \
        ull a0_ = ffma2(hvA_, rwr0.x, GFOLD(G0_)); a0_ = ffma2(hvB_, rwr0.y, a0_);                    \
        ull a1_ = ffma2(hvA_, rwr1.x, GFOLD(G1_)); a1_ = ffma2(hvB_, rwr1.y, a1_);                    \
        ull a2_ = ffma2(hvA_, rwr2.x, GFOLD(G2_)); a2_ = ffma2(hvB_, rwr2.y, a2_);                    \
        ull a3_ = ffma2(hvA_, rwr3.x, GFOLD(G3_)); a3_ = ffma2(hvB_, rwr3.y, a3_);                    \
        mbar_wait_parity((BARADDR), (PAR));                                                           \
        if ((DO_EXPECT) && tid == 0) mbar_expect_tx((BARADDR), 1024);                                 \
        const char* hbb_ = (const char*)sh + (SH_OFF);                                                \
        _Pragma("unroll")                                                                             \
        for (int i_ = 0; i_ < 7; i_++) {                                                              \
            ulonglong2 hv_ = *(const ulonglong2*)(hbb_ + offs[i_]);                                   \
            a0_ = ffma2(hv_.x, rw0[i_].x, a0_); a0_ = ffma2(hv_.y, rw0[i_].y, a0_);                   \
            a1_ = ffma2(hv_.x, rw1[i_].x, a1_); a1_ = ffma2(hv_.y, rw1[i_].y, a1_);                   \
            a2_ = ffma2(hv_.x, rw2[i_].x, a2_); a2_ = ffma2(hv_.y, rw2[i_].y, a2_);                   \
            a3_ = ffma2(hv_.x, rw3[i_].x, a3_); a3_ = ffma2(hv_.y, rw3[i_].y, a3_);                   \
        }                                                                                             \
        float s0_ = f2sum(a0_), s1_ = f2sum(a1_), s2_ = f2sum(a2_), s3_ = f2sum(a3_);                 \
        _Pragma("unroll")                                                                             \
        for (int off_ = 1; off_ <= 4; off_ <<= 1) {                                                   \
            s0_ += __shfl_xor_sync(0xFFFFFFFFu, s0_, off_);                                           \
            s1_ += __shfl_xor_sync(0xFFFFFFFFu, s1_, off_);                                           \
            s2_ += __shfl_xor_sync(0xFFFFFFFFu, s2_, off_);                                           \
            s3_ += __shfl_xor_sync(0xFFFFFFFFu, s3_, off_);                                           \
        }                                                                                             \
        c = fmaf(sigm(s1_), c, sigm(s0_) * tanha(s2_));                                               \
        float h_ = sigm(s3_) * tanha(c);                                                              \
        if (DO_STORE)                                                                                 \
            st_async_b32(dst_my - (ST_DOFF), h_, bar_my - (ST_BOFF));                                 \
        if (is_writer)                                                                                \
            gwp[(size_t)(TIDX) * HW] = h_;                                                            \
        if (DO_BAR) {                                                                                 \
            if (is_writer) hloc[HLW_][jj] = h_;                                                       \
            __syncthreads();                                                                          \
        }                                                                                             \
    } while (0)

__global__ void __launch_bounds__(256, 1) __cluster_dims__(8, 1, 1)
mega_kernel(const float* __restrict__ Whh,
            const int* __restrict__ widx, const float* __restrict__ wemb,
            const float* __restrict__ Wih,
            const float* __restrict__ bih, const float* __restrict__ bhh,
            const float* __restrict__ tagW, const float* __restrict__ tagb,
            float* __restrict__ out)
{
    extern __shared__ float dynsm[];
    __shared__ float sh[2][256];
    __shared__ float hloc[2][32];
    __shared__ __align__(8) unsigned long long bar2[2];
    __shared__ int s_u;

    const int tid = threadIdx.x;

    if (blockIdx.x < 8) {
        // ================= WORD RECURRENCE (cluster 0) =================
        const int jj  = tid >> 3;
        const int oct = tid & 7;
        const uint32_t rank = cluster_rank();
        const int uglob = (int)rank * 32 + jj;

        ulonglong2 rw0[7], rw1[7], rw2[7], rw3[7];
        ulonglong2 rwr0, rwr1, rwr2, rwr3;
        uint32_t offs[7];
        {
            const float* base = Whh + (size_t)uglob * 256 + oct * 4;
            rwr0 = *(const ulonglong2*)(base + 0 * 65536 + (int)rank * 32);
            rwr1 = *(const ulonglong2*)(base + 1 * 65536 + (int)rank * 32);
            rwr2 = *(const ulonglong2*)(base + 2 * 65536 + (int)rank * 32);
            rwr3 = *(const ulonglong2*)(base + 3 * 65536 + (int)rank * 32);
            int j = 0;
            for (int mm = 0; mm < 8; mm++) {
                if (mm == (int)rank) continue;
                rw0[j] = *(const ulonglong2*)(base + 0 * 65536 + mm * 32);
                rw1[j] = *(const ulonglong2*)(base + 1 * 65536 + mm * 32);
                rw2[j] = *(const ulonglong2*)(base + 2 * 65536 + mm * 32);
                rw3[j] = *(const ulonglong2*)(base + 3 * 65536 + mm * 32);
                offs[j] = (uint32_t)(oct + mm * 8) * 16u;
                j++;
            }
        }

        sh[0][tid] = 0.f;
        sh[1][tid] = 0.f;
        if (tid < 64) hloc[tid >> 5][tid & 31] = 0.f;
        const uint32_t locb0 = smem_u32(&bar2[0]);
        const uint32_t locb1 = smem_u32(&bar2[1]);
        if (tid == 0) {
            mbar_init(locb0, 1);
            mbar_init(locb1, 1);
            mbar_expect_tx(locb0, 1024);
            mbar_expect_tx(locb1, 1024);
        }
        __syncthreads();
        cluster_sync_();

        const uint32_t dst_my = mapa_sh(smem_u32(&sh[1][uglob]), (uint32_t)oct);
        const uint32_t bar_my = mapa_sh(locb1, (uint32_t)oct);

        float c = 0.f;
        const bool is_writer = (oct == 0);
        float* const gwp = g_wh + uglob;

        // wait for gpre chunk 0 (tokens 0..127)
        wait_ge(&g_sync[2], 128);

        // ---------- t = 0 ----------
        {
            const float* gpp0 = g_gpre + uglob;
            float gp0 = gpp0[0], gp2 = gpp0[512], gp3 = gpp0[768];
            c = sigm(gp0) * tanha(gp2);
            float h = sigm(gp3) * tanha(c);
            st_async_b32(dst_my, h, bar_my);
            if (is_writer) { gwp[0] = h; hloc[0][jj] = h; }
            __syncthreads();
        }

        // ---------- interior: chunk-outer, branch-free inner ----------
        const float* gpp = g_gpre + 1024 + uglob;
        float A0, A1, A2, A3;
        float B0, B1, B2, B3;
        A0 = gpp[0];    A1 = gpp[256];  A2 = gpp[512];  A3 = gpp[768];
        B0 = gpp[1024]; B1 = gpp[1280]; B2 = gpp[1536]; B3 = gpp[1792];

        int m = 0;
        for (int ck = 0; ck < 64; ck++) {
            // poll next gpre chunk at the boundary (covers this chunk's prefetches)
            if (ck < 63) wait_ge(&g_sync[2 + ck + 1], 128);
            const int mend = (ck == 63) ? 4094 : (ck * 64 + 64);

            for (; m < mend; m++) {          // branch-free body
                const float* np = gpp + 2048;
                float N0 = np[0],    N1 = np[256],  N2 = np[512],  N3 = np[768];
                float M0 = np[1024], M1 = np[1280], M2 = np[1536], M3 = np[1792];
                const uint32_t ph = (uint32_t)m & 1u;

                WSTEP(locb1, ph, A0, A1, A2, A3, 1024u, 1024u, 8u, 2 * m + 1, 1, 1, 0, 1, 1);
                WSTEP(locb0, ph, B0, B1, B2, B3, 0u, 0u, 0u, 2 * m + 2, 1, 1, 1, 0, 1);

                A0 = N0; A1 = N1; A2 = N2; A3 = N3;
                B0 = M0; B1 = M1; B2 = M2; B3 = M3;
                gpp += 2048;
            }

            // signal g_wh chunk ck complete (tokens <= 128*ck+128) — not for ck=63
            if (ck < 63) {
                __threadfence();
                __syncthreads();
                if (tid == 0) atomicAdd(&g_sync[66 + ck], 1);
            }
        }

        // ---------- tail: t = 8189, 8190, 8191 ----------
        {
            const float* fp = gpp + 2048;
            float F0 = fp[0], F1 = fp[256], F2 = fp[512], F3 = fp[768];
            WSTEP(locb1, 0u, A0, A1, A2, A3, 1024u, 1024u, 8u, 8189, 1, 1, 0, 1, 1);
            WSTEP(locb0, 0u, B0, B1, B2, B3, 0u, 0u, 0u, 8190, 1, 1, 1, 0, 1);
            WSTEP(locb1, 1u, F0, F1, F2, F3, 1024u, 0u, 0u, 8191, 0, 0, 0, 1, 0);
        }
        __threadfence();
        __syncthreads();
        if (tid == 0) atomicAdd(&g_sync[66 + 63], 1);
        return;
    }

    // ================= WORKERS (clusters 1..16) =================
    // ---- phase 1: gpre producers (work-steal 8192 units of 16t x 64G) ----
    {
        float* sx = dynsm;            // [16][196]
        float* sw = dynsm + 16 * BP;  // [64][196]
        for (;;) {
            if (tid == 0) s_u = atomicAdd(&g_sync[0], 1);
            __syncthreads();
            const int u = s_u;
            if (u >= 8192) break;
            const int t0 = (u >> 4) * 16;
            const int G0 = (u & 15) * 64;

            for (int i = tid; i < 16 * 48; i += 256) {
                int tt = i / 48, k4 = i % 48;
                float4 v = (k4 < 32)
                    ? *(const float4*)(wemb + (size_t)widx[t0 + tt] * 128 + k4 * 4)
                    : *(const float4*)(g_char_feat + (size_t)(t0 + tt) * 64 + (k4 - 32) * 4);
                *(float4*)&sx[tt * BP + k4 * 4] = v;
            }
            for (int i = tid; i < 64 * 48; i += 256) {
                int r = i / 48, k4 = i % 48;
                *(float4*)&sw[r * BP + k4 * 4] = *(const float4*)(Wih + (size_t)(G0 + r) * 192 + k4 * 4);
            }
            __syncthreads();

            const int g = tid & 63, tq = tid >> 6;
            ull ax[4], ay[4];
            #pragma unroll
            for (int i = 0; i < 4; i++) { ax[i] = 0ull; ay[i] = 0ull; }

            #pragma unroll 4
            for (int k4 = 0; k4 < 48; k4++) {
                ulonglong2 wv = *(const ulonglong2*)&sw[g * BP + k4 * 4];
                #pragma unroll
                for (int it = 0; it < 4; it++) {
                    ulonglong2 xv = *(const ulonglong2*)&sx[(tq * 4 + it) * BP + k4 * 4];
                    ax[it] = ffma2(xv.x, wv.x, ax[it]);
                    ay[it] = ffma2(xv.y, wv.y, ay[it]);
                }
            }
            float b = bih[G0 + g] + bhh[G0 + g];
            #pragma unroll
            for (int it = 0; it < 4; it++)
                g_gpre[(size_t)(t0 + tq * 4 + it) * 1024 + G0 + g] = f2sum(ax[it]) + f2sum(ay[it]) + b;

            __threadfence();
            __syncthreads();
            if (tid == 0) atomicAdd(&g_sync[2 + (t0 >> 7)], 1);
        }
    }

    // ---- phase 2: tag consumers (work-steal 64 chunks of 128 tokens) ----
    {
        float* tsw = dynsm;            // [256][64] transposed tagW
        float* tsb = dynsm + TAG_SW;   // [64]
        __syncthreads();
        for (int i = tid; i < TAG_SW; i += 256) tsw[i] = 0.f;
        if (tid < 64) tsb[tid] = (tid < TAGS) ? tagb[tid] : 0.f;
        __syncthreads();
        for (int i = tid; i < TAGS * 256; i += 256) {
            int tg = i >> 8, k = i & 255;
            tsw[k * 64 + tg] = tagW[i];
        }
        __syncthreads();

        const int lane = tid & 31, warp = tid >> 5;
        const bool v1 = (32 + lane) < TAGS;

        for (;;) {
            if (tid == 0) s_u = atomicAdd(&g_sync[1], 1);
            __syncthreads();
            const int ck = s_u;
            if (ck >= 64) break;
            wait_ge_sleep(&g_sync[66 + ck], 8);

            #pragma unroll 1
            for (int it = 0; it < 16; it++) {
                const int token = ck * 128 + it * 8 + warp;
                const float4* hp4 = (const float4*)(g_wh + (size_t)token * 256);

                float a0 = 0.f, a1 = 0.f;
                #pragma unroll 8
                for (int k4 = 0; k4 < 64; k4++) {
                    float4 h = hp4[k4];
                    const float* p = tsw + k4 * 256 + lane;
                    a0 = fmaf(h.x, p[0],   a0);  a1 = fmaf(h.x, p[32],  a1);
                    a0 = fmaf(h.y, p[64],  a0);  a1 = fmaf(h.y, p[96],  a1);
                    a0 = fmaf(h.z, p[128], a0);  a1 = fmaf(h.z, p[160], a1);
                    a0 = fmaf(h.w, p[192], a0);  a1 = fmaf(h.w, p[224], a1);
                }
                a0 += tsb[lane];
                a1 += tsb[32 + lane];

                float mx = fmaxf(a0, v1 ? a1 : -3.4e38f);
                #pragma unroll
                for (int off = 16; off; off >>= 1)
                    mx = fmaxf(mx, __shfl_xor_sync(0xFFFFFFFFu, mx, off));
                float e = __expf(a0 - mx) + (v1 ? __expf(a1 - mx) : 0.f);
                #pragma unroll
                for (int off = 16; off; off >>= 1)
                    e += __shfl_xor_sync(0xFFFFFFFFu, e, off);
                float ls = __logf(e);

                out[(size_t)token * TAGS + lane] = a0 - mx - ls;
                if (v1) out[(size_t)token * TAGS + 32 + lane] = a1 - mx - ls;
            }
        }
    }
}

// =====================================================================
extern "C" void kernel_launch(void* const* d_in, const int* in_sizes, int n_in,
                              void* d_out, int out_size)
{
    const int*   word_idxs = (const int*)d_in[0];
    const int*   char_idxs = (const int*)d_in[1];
    const int*   char_lens = (const int*)d_in[2];
    const float* char_emb  = (const float*)d_in[3];
    const float* char_Wih  = (const float*)d_in[4];
    const float* char_Whh  = (const float*)d_in[5];
    const float* char_bih  = (const float*)d_in[6];
    const float* char_bhh  = (const float*)d_in[7];
    const float* word_emb  = (const float*)d_in[8];
    const float* word_Wih  = (const float*)d_in[9];
    const float* word_Whh  = (const float*)d_in[10];
    const float* word_bih  = (const float*)d_in[11];
    const float* word_bhh  = (const float*)d_in[12];
    const float* tag_W     = (const float*)d_in[13];
    const float* tag_b     = (const float*)d_in[14];
    float* out = (float*)d_out;

    void* sync_addr = nullptr;
    cudaGetSymbolAddress(&sync_addr, g_sync);
    cudaMemsetAsync(sync_addr, 0, sizeof(int) * 160);

    cudaFuncSetAttribute(char_lstm_kernel,
                         cudaFuncAttributeMaxDynamicSharedMemorySize, CHAR_SMEM_BYTES);
    cudaFuncSetAttribute(mega_kernel,
                         cudaFuncAttributeMaxDynamicSharedMemorySize, MEGA_DYN_BYTES);

    char_lstm_kernel<<<256, 512, CHAR_SMEM_BYTES>>>(
        char_idxs, char_lens, char_emb, char_Wih, char_Whh, char_bih, char_bhh);

    mega_kernel<<<136, 256, MEGA_DYN_BYTES>>>(
        word_Whh, word_idxs, word_emb, word_Wih, word_bih, word_bhh,
        tag_W, tag_b, out);
}

// round 17
// speedup vs baseline: 1.2142x; 1.0004x over previous
#include <cuda_runtime.h>
#include <cstdint>
#include <cstddef>

#define S     8192
#define LC    16
#define CH    64
#define HW    256
#define TAGS  50

typedef unsigned long long ull;

// ---------------- device scratch ----------------
__device__ __align__(256) float g_char_feat[S * CH];        // 2 MB
__device__ __align__(256) float g_gpre[(size_t)S * 4 * HW]; // 32 MB
__device__ __align__(256) float g_wh[(size_t)S * HW];       // 8 MB

// sync state, zeroed each launch via cudaMemsetAsync:
// [0] = gpre unit counter, [1] = tag chunk counter,
// [2..65]    = gpre chunk-done counts   (64 chunks of 128 tokens, target 128)
// [66..129]  = g_wh chunk-done counts   (64 chunks of 128 tokens, target 8)
// [130]      = char unit counter
// [131..194] = char chunk-done counts   (64 chunks of 128 tokens, target 8)
__device__ __align__(256) int g_sync[256];

// ---------------- helpers ----------------
__device__ __forceinline__ ull ffma2(ull a, ull b, ull c) {
    ull d;
    asm("fma.rn.f32x2 %0, %1, %2, %3;" : "=l"(d) : "l"(a), "l"(b), "l"(c));
    return d;
}
__device__ __forceinline__ ull packf2(float lo, float hi) {
    ull r;
    asm("mov.b64 %0, {%1, %2};" : "=l"(r) : "f"(lo), "f"(hi));
    return r;
}
__device__ __forceinline__ float f2sum(ull a) {
    float lo = __uint_as_float((unsigned)(a & 0xffffffffull));
    float hi = __uint_as_float((unsigned)(a >> 32));
    return lo + hi;
}
__device__ __forceinline__ float tanha(float x) {
    float y; asm("tanh.approx.f32 %0, %1;" : "=f"(y) : "f"(x)); return y;
}
__device__ __forceinline__ float sigm(float x) {
    return fmaf(0.5f, tanha(0.5f * x), 0.5f);
}
__device__ __forceinline__ uint32_t smem_u32(const void* p) {
    return (uint32_t)__cvta_generic_to_shared(p);
}
__device__ __forceinline__ uint32_t cluster_rank() {
    uint32_t r; asm("mov.u32 %0, %%cluster_ctarank;" : "=r"(r)); return r;
}
__device__ __forceinline__ uint32_t mapa_sh(uint32_t addr, uint32_t rank) {
    uint32_t r;
    asm("mapa.shared::cluster.u32 %0, %1, %2;" : "=r"(r) : "r"(addr), "r"(rank));
    return r;
}
__device__ __forceinline__ void mbar_init(uint32_t addr, uint32_t cnt) {
    asm volatile("mbarrier.init.shared.b64 [%0], %1;" :: "r"(addr), "r"(cnt) : "memory");
}
__device__ __forceinline__ void mbar_expect_tx(uint32_t addr, uint32_t bytes) {
    asm volatile("mbarrier.arrive.expect_tx.shared.b64 _, [%0], %1;"
                 :: "r"(addr), "r"(bytes) : "memory");
}
__device__ __forceinline__ void st_async_b32(uint32_t dst, float v, uint32_t mbar) {
    asm volatile("st.async.shared::cluster.mbarrier::complete_tx::bytes.b32 [%0], %1, [%2];"
                 :: "r"(dst), "r"(__float_as_uint(v)), "r"(mbar) : "memory");
}
__device__ __forceinline__ void mbar_wait_parity(uint32_t mbar, uint32_t parity) {
    asm volatile(
        "{\n\t.reg .pred P;\n"
        "W%=:\n\t"
        "mbarrier.try_wait.parity.acquire.cluster.shared::cta.b64 P, [%0], %1, 0x989680;\n\t"
        "@!P bra W%=;\n\t"
        "}" :: "r"(mbar), "r"(parity) : "memory");
}
__device__ __forceinline__ void cluster_sync_() {
    asm volatile("barrier.cluster.arrive.aligned;\n\tbarrier.cluster.wait.aligned;" ::: "memory");
}
__device__ __forceinline__ void named_bar(int id, int cnt) {
    asm volatile("bar.sync %0, %1;" :: "r"(id), "r"(cnt) : "memory");
}
__device__ __forceinline__ int ld_acq(const int* p) {
    int v;
    asm volatile("ld.acquire.gpu.global.s32 %0, [%1];" : "=r"(v) : "l"(p) : "memory");
    return v;
}
__device__ __forceinline__ void wait_ge(const int* p, int tgt) {
    while (ld_acq(p) < tgt) { }
}
__device__ __forceinline__ void wait_ge_sleep(const int* p, int tgt) {
    while (ld_acq(p) < tgt) __nanosleep(1000);
}

// =====================================================================
// Mega kernel: 17 clusters x 8 CTAs. Everything fused.
//   cluster 0: word recurrence, chunk-outer / branch-free-inner.
//   clusters 1..16 (128 CTAs), three phases:
//     0: work-steal 512 char units (16 words each); signal char chunks
//     1: work-steal 8192 gpre units (wait on char chunks); signal gpre chunks
//     2: work-steal 64 tag chunks (wait on g_wh chunks)
// =====================================================================
#define BP 196
#define TAG_SW     (256 * 64)
// char smem (floats): sW 512*68 + cemb 128*64 + hbuf 16*64 + sb 256 = 44288
// + ints: scidx 256 + lens 16 + sort 16 = 288
#define CH_SW    (512 * 68)
#define CH_EMB   (128 * 64)
#define CH_HB    (16 * 64)
#define CH_FLOATS (CH_SW + CH_EMB + CH_HB + 256)
#define MEGA_DYN_BYTES (CH_FLOATS * 4 + 288 * 4)   // ~178.3 KB (max of all phases)

#define GFOLD(G_) ((oct == 0) ? (ull)__float_as_uint(G_) : 0ull)

#define WSTEP(BARADDR, PAR, G0_, G1_, G2_, G3_, SH_OFF, ST_DOFF, ST_BOFF, TIDX, DO_EXPECT, DO_STORE, HLR_, HLW_, DO_BAR) \
    do {                                                                                              \
        float4 hl_ = *(const float4*)&hloc[HLR_][oct * 4];                                            \
        ull hvA_ = packf2(hl_.x, hl_.y), hvB_ = packf2(hl_.z, hl_.w);                                 \
        ull a0_ = ffma2(hvA_, rwr0.x, GFOLD(G0_)); a0_ = ffma2(hvB_, rwr0.y, a0_);                    \
        ull a1_ = ffma2(hvA_, rwr1.x, GFOLD(G1_)); a1_ = ffma2(hvB_, rwr1.y, a1_);                    \
        ull a2_ = ffma2(hvA_, rwr2.x, GFOLD(G2_)); a2_ = ffma2(hvB_, rwr2.y, a2_);                    \
        ull a3_ = ffma2(hvA_, rwr3.x, GFOLD(G3_)); a3_ = ffma2(hvB_, rwr3.y, a3_);                    \
        mbar_wait_parity((BARADDR), (PAR));                                                           \
        if ((DO_EXPECT) && tid == 0) mbar_expect_tx((BARADDR), 1024);                                 \
        const char* hbb_ = (const char*)sh + (SH_OFF);                                                \
        _Pragma("unroll")                                                                             \
        for (int i_ = 0; i_ < 7; i_++) {                                                              \
            ulonglong2 hv_ = *(const ulonglong2*)(hbb_ + offs[i_]);                                   \
            a0_ = ffma2(hv_.x, rw0[i_].x, a0_); a0_ = ffma2(hv_.y, rw0[i_].y, a0_);                   \
            a1_ = ffma2(hv_.x, rw1[i_].x, a1_); a1_ = ffma2(hv_.y, rw1[i_].y, a1_);                   \
            a2_ = ffma2(hv_.x, rw2[i_].x, a2_); a2_ = ffma2(hv_.y, rw2[i_].y, a2_);                   \
            a3_ = ffma2(hv_.x, rw3[i_].x, a3_); a3_ = ffma2(hv_.y, rw3[i_].y, a3_);                   \
        }                                                                                             \
        float s0_ = f2sum(a0_), s1_ = f2sum(a1_), s2_ = f2sum(a2_), s3_ = f2sum(a3_);                 \
        _Pragma("unroll")                                                                             \
        for (int off_ = 1; off_ <= 4; off_ <<= 1) {                                                   \
            s0_ += __shfl_xor_sync(0xFFFFFFFFu, s0_, off_);                                           \
            s1_ += __shfl_xor_sync(0xFFFFFFFFu, s1_, off_);                                           \
            s2_ += __shfl_xor_sync(0xFFFFFFFFu, s2_, off_);                                           \
            s3_ += __shfl_xor_sync(0xFFFFFFFFu, s3_, off_);                                           \
        }                                                                                             \
        c = fmaf(sigm(s1_), c, sigm(s0_) * tanha(s2_));                                               \
        float h_ = sigm(s3_) * tanha(c);                                                              \
        if (DO_STORE)                                                                                 \
            st_async_b32(dst_my - (ST_DOFF), h_, bar_my - (ST_BOFF));                                 \
        if (is_writer)                                                                                \
            gwp[(size_t)(TIDX) * HW] = h_;                                                            \
        if (DO_BAR) {                                                                                 \
            if (is_writer) hloc[HLW_][jj] = h_;                                                       \
            __syncthreads();                                                                          \
        }                                                                                             \
    } while (0)

__global__ void __launch_bounds__(256, 1) __cluster_dims__(8, 1, 1)
mega_kernel(const float* __restrict__ Whh,
            const int* __restrict__ widx, const float* __restrict__ wemb,
            const float* __restrict__ Wih,
            const float* __restrict__ bih, const float* __restrict__ bhh,
            const float* __restrict__ tagW, const float* __restrict__ tagb,
            const int* __restrict__ ci_g, const int* __restrict__ clen,
            const float* __restrict__ cemb_g,
            const float* __restrict__ cWih, const float* __restrict__ cWhh,
            const float* __restrict__ cbih, const float* __restrict__ cbhh,
            float* __restrict__ out)
{
    extern __shared__ float dynsm[];
    __shared__ float sh[2][256];
    __shared__ float hloc[2][32];
    __shared__ __align__(8) unsigned long long bar2[2];
    __shared__ int s_u;

    const int tid = threadIdx.x;

    if (blockIdx.x < 8) {
        // ================= WORD RECURRENCE (cluster 0) =================
        const int jj  = tid >> 3;
        const int oct = tid & 7;
        const uint32_t rank = cluster_rank();
        const int uglob = (int)rank * 32 + jj;

        ulonglong2 rw0[7], rw1[7], rw2[7], rw3[7];
        ulonglong2 rwr0, rwr1, rwr2, rwr3;
        uint32_t offs[7];
        {
            const float* base = Whh + (size_t)uglob * 256 + oct * 4;
            rwr0 = *(const ulonglong2*)(base + 0 * 65536 + (int)rank * 32);
            rwr1 = *(const ulonglong2*)(base + 1 * 65536 + (int)rank * 32);
            rwr2 = *(const ulonglong2*)(base + 2 * 65536 + (int)rank * 32);
            rwr3 = *(const ulonglong2*)(base + 3 * 65536 + (int)rank * 32);
            int j = 0;
            for (int mm = 0; mm < 8; mm++) {
                if (mm == (int)rank) continue;
                rw0[j] = *(const ulonglong2*)(base + 0 * 65536 + mm * 32);
                rw1[j] = *(const ulonglong2*)(base + 1 * 65536 + mm * 32);
                rw2[j] = *(const ulonglong2*)(base + 2 * 65536 + mm * 32);
                rw3[j] = *(const ulonglong2*)(base + 3 * 65536 + mm * 32);
                offs[j] = (uint32_t)(oct + mm * 8) * 16u;
                j++;
            }
        }

        sh[0][tid] = 0.f;
        sh[1][tid] = 0.f;
        if (tid < 64) hloc[tid >> 5][tid & 31] = 0.f;
        const uint32_t locb0 = smem_u32(&bar2[0]);
        const uint32_t locb1 = smem_u32(&bar2[1]);
        if (tid == 0) {
            mbar_init(locb0, 1);
            mbar_init(locb1, 1);
            mbar_expect_tx(locb0, 1024);
            mbar_expect_tx(locb1, 1024);
        }
        __syncthreads();
        cluster_sync_();

        const uint32_t dst_my = mapa_sh(smem_u32(&sh[1][uglob]), (uint32_t)oct);
        const uint32_t bar_my = mapa_sh(locb1, (uint32_t)oct);

        float c = 0.f;
        const bool is_writer = (oct == 0);
        float* const gwp = g_wh + uglob;

        // wait for gpre chunk 0 (tokens 0..127)
        wait_ge(&g_sync[2], 128);

        // ---------- t = 0 ----------
        {
            const float* gpp0 = g_gpre + uglob;
            float gp0 = gpp0[0], gp2 = gpp0[512], gp3 = gpp0[768];
            c = sigm(gp0) * tanha(gp2);
            float h = sigm(gp3) * tanha(c);
            st_async_b32(dst_my, h, bar_my);
            if (is_writer) { gwp[0] = h; hloc[0][jj] = h; }
            __syncthreads();
        }

        // ---------- interior: chunk-outer, branch-free inner ----------
        const float* gpp = g_gpre + 1024 + uglob;
        float A0, A1, A2, A3;
        float B0, B1, B2, B3;
        A0 = gpp[0];    A1 = gpp[256];  A2 = gpp[512];  A3 = gpp[768];
        B0 = gpp[1024]; B1 = gpp[1280]; B2 = gpp[1536]; B3 = gpp[1792];

        int m = 0;
        for (int ck = 0; ck < 64; ck++) {
            if (ck < 63) wait_ge(&g_sync[2 + ck + 1], 128);
            const int mend = (ck == 63) ? 4094 : (ck * 64 + 64);

            for (; m < mend; m++) {          // branch-free body
                const float* np = gpp + 2048;
                float N0 = np[0],    N1 = np[256],  N2 = np[512],  N3 = np[768];
                float M0 = np[1024], M1 = np[1280], M2 = np[1536], M3 = np[1792];
                const uint32_t ph = (uint32_t)m & 1u;

                WSTEP(locb1, ph, A0, A1, A2, A3, 1024u, 1024u, 8u, 2 * m + 1, 1, 1, 0, 1, 1);
                WSTEP(locb0, ph, B0, B1, B2, B3, 0u, 0u, 0u, 2 * m + 2, 1, 1, 1, 0, 1);

                A0 = N0; A1 = N1; A2 = N2; A3 = N3;
                B0 = M0; B1 = M1; B2 = M2; B3 = M3;
                gpp += 2048;
            }

            if (ck < 63) {
                __threadfence();
                __syncthreads();
                if (tid == 0) atomicAdd(&g_sync[66 + ck], 1);
            }
        }

        // ---------- tail: t = 8189, 8190, 8191 ----------
        {
            const float* fp = gpp + 2048;
            float F0 = fp[0], F1 = fp[256], F2 = fp[512], F3 = fp[768];
            WSTEP(locb1, 0u, A0, A1, A2, A3, 1024u, 1024u, 8u, 8189, 1, 1, 0, 1, 1);
            WSTEP(locb0, 0u, B0, B1, B2, B3, 0u, 0u, 0u, 8190, 1, 1, 1, 0, 1);
            WSTEP(locb1, 1u, F0, F1, F2, F3, 1024u, 0u, 0u, 8191, 0, 0, 0, 1, 0);
        }
        __threadfence();
        __syncthreads();
        if (tid == 0) atomicAdd(&g_sync[66 + 63], 1);
        return;
    }

    // ================= WORKERS (clusters 1..16) =================
    // ---- phase 0: char LSTM (work-steal 512 units of 16 words) ----
    {
        float* sW    = dynsm;                   // [512][68]
        float* cemb  = sW + CH_SW;              // [128][64]
        float* hbuf  = cemb + CH_EMB;           // [16][64]
        float* sb    = hbuf + CH_HB;            // [256]
        int*   scidx = (int*)(sb + 256);        // [16][16]
        int*   slens = scidx + 256;             // [16]
        int*   ssort = slens + 16;              // [16]

        // stage weights + embedding table ONCE per CTA
        for (int idx = tid; idx < 512 * 16; idx += 256) {
            int row = idx >> 4, k4 = idx & 15;
            const float* src = (row < 256) ? cWih + (size_t)row * 64 + k4 * 4
                                           : cWhh + (size_t)(row - 256) * 64 + k4 * 4;
            *(float4*)&sW[row * 68 + k4 * 4] = *(const float4*)src;
        }
        for (int idx = tid; idx < 128 * 16; idx += 256) {
            int row = idx >> 4, k4 = idx & 15;
            *(float4*)&cemb[row * 64 + k4 * 4] = *(const float4*)(cemb_g + (size_t)row * 64 + k4 * 4);
        }
        sb[tid] = cbih[tid] + cbhh[tid];
        __syncthreads();

        const int rt = tid & 63, wt = tid >> 6, w0 = wt * 4;
        const int perm4[4] = {0, 1, 3, 2};   // SMSP-pair balance
        const int q0 = perm4[wt] * 4;
        const int barid = wt + 1;

        for (;;) {
            if (tid == 0) s_u = atomicAdd(&g_sync[130], 1);
            __syncthreads();
            const int cu = s_u;
            if (cu >= 512) break;
            const int wbase = cu * 16;

            scidx[tid] = ci_g[(size_t)wbase * 16 + tid];
            if (tid < 16) slens[tid] = clen[wbase + tid];
            for (int idx = tid; idx < CH_HB; idx += 256) hbuf[idx] = 0.f;
            __syncthreads();

            if (tid < 16) {
                int ml = slens[tid];
                int rank = 0;
                #pragma unroll
                for (int j = 0; j < 16; j++) {
                    int lj = slens[j];
                    rank += (lj < ml || (lj == ml && j < tid)) ? 1 : 0;
                }
                ssort[rank] = tid;
            }
            __syncthreads();

            int wloc[4], len[4]; float cc[4];
            #pragma unroll
            for (int i = 0; i < 4; i++) {
                wloc[i] = ssort[q0 + i];
                len[i]  = slens[wloc[i]];
                cc[i]   = 0.f;
            }
            const int tmax = len[3];   // ascending within quartet

            for (int t = 0; t < tmax; t++) {
                int ci[4];
                #pragma unroll
                for (int i = 0; i < 4; i++) ci[i] = scidx[wloc[i] * 16 + t];

                ull acc[4][4];
                #pragma unroll
                for (int i = 0; i < 4; i++)
                    #pragma unroll
                    for (int q = 0; q < 4; q++) acc[i][q] = 0ull;

                #pragma unroll
                for (int k4 = 0; k4 < 16; k4++) {
                    ulonglong2 wv[4];
                    #pragma unroll
                    for (int q = 0; q < 4; q++)
                        wv[q] = *(const ulonglong2*)&sW[(q * 64 + rt) * 68 + k4 * 4];
                    #pragma unroll
                    for (int i = 0; i < 4; i++) {
                        ulonglong2 xv = *(const ulonglong2*)&cemb[ci[i] * 64 + k4 * 4];
                        #pragma unroll
                        for (int q = 0; q < 4; q++) {
                            acc[i][q] = ffma2(xv.x, wv[q].x, acc[i][q]);
                            acc[i][q] = ffma2(xv.y, wv[q].y, acc[i][q]);
                        }
                    }
                }
                #pragma unroll
                for (int k4 = 0; k4 < 16; k4++) {
                    ulonglong2 wv[4];
                    #pragma unroll
                    for (int q = 0; q < 4; q++)
                        wv[q] = *(const ulonglong2*)&sW[(256 + q * 64 + rt) * 68 + k4 * 4];
                    #pragma unroll
                    for (int i = 0; i < 4; i++) {
                        ulonglong2 hv = *(const ulonglong2*)&hbuf[(w0 + i) * 64 + k4 * 4];
                        #pragma unroll
                        for (int q = 0; q < 4; q++) {
                            acc[i][q] = ffma2(hv.x, wv[q].x, acc[i][q]);
                            acc[i][q] = ffma2(hv.y, wv[q].y, acc[i][q]);
                        }
                    }
                }
                named_bar(barid, 64);

                float bI = sb[rt], bF = sb[64 + rt], bG = sb[128 + rt], bO = sb[192 + rt];
                #pragma unroll
                for (int i = 0; i < 4; i++) {
                    float gi = f2sum(acc[i][0]) + bI;
                    float gf = f2sum(acc[i][1]) + bF;
                    float gG = f2sum(acc[i][2]) + bG;
                    float go = f2sum(acc[i][3]) + bO;
                    cc[i] = fmaf(sigm(gf), cc[i], sigm(gi) * tanha(gG));
                    float h = sigm(go) * tanha(cc[i]);
                    hbuf[(w0 + i) * 64 + rt] = h;
                    if (t == len[i] - 1)
                        g_char_feat[(size_t)(wbase + wloc[i]) * 64 + rt] = h;
                }
                named_bar(barid, 64);
            }

            __threadfence();
            __syncthreads();
            if (tid == 0) atomicAdd(&g_sync[131 + (cu >> 3)], 1);
        }
    }

    // ---- phase 1: gpre producers (work-steal 8192 units of 16t x 64G) ----
    {
        float* sx = dynsm;            // [16][196]
        float* sw = dynsm + 16 * BP;  // [64][196]
        __syncthreads();              // done with char smem
        for (;;) {
            if (tid == 0) s_u = atomicAdd(&g_sync[0], 1);
            __syncthreads();
            const int u = s_u;
            if (u >= 8192) break;
            const int t0 = (u >> 4) * 16;
            const int G0 = (u & 15) * 64;

            // char features for tokens t0..t0+15 must be ready
            wait_ge(&g_sync[131 + (u >> 7)], 8);

            for (int i = tid; i < 16 * 48; i += 256) {
                int tt = i / 48, k4 = i % 48;
                float4 v = (k4 < 32)
                    ? *(const float4*)(wemb + (size_t)widx[t0 + tt] * 128 + k4 * 4)
                    : *(const float4*)(g_char_feat + (size_t)(t0 + tt) * 64 + (k4 - 32) * 4);
                *(float4*)&sx[tt * BP + k4 * 4] = v;
            }
            for (int i = tid; i < 64 * 48; i += 256) {
                int r = i / 48, k4 = i % 48;
                *(float4*)&sw[r * BP + k4 * 4] = *(const float4*)(Wih + (size_t)(G0 + r) * 192 + k4 * 4);
            }
            __syncthreads();

            const int g = tid & 63, tq = tid >> 6;
            ull ax[4], ay[4];
            #pragma unroll
            for (int i = 0; i < 4; i++) { ax[i] = 0ull; ay[i] = 0ull; }

            #pragma unroll 4
            for (int k4 = 0; k4 < 48; k4++) {
                ulonglong2 wv = *(const ulonglong2*)&sw[g * BP + k4 * 4];
                #pragma unroll
                for (int it = 0; it < 4; it++) {
                    ulonglong2 xv = *(const ulonglong2*)&sx[(tq * 4 + it) * BP + k4 * 4];
                    ax[it] = ffma2(xv.x, wv.x, ax[it]);
                    ay[it] = ffma2(xv.y, wv.y, ay[it]);
                }
            }
            float b = bih[G0 + g] + bhh[G0 + g];
            #pragma unroll
            for (int it = 0; it < 4; it++)
                g_gpre[(size_t)(t0 + tq * 4 + it) * 1024 + G0 + g] = f2sum(ax[it]) + f2sum(ay[it]) + b;

            __threadfence();
            __syncthreads();
            if (tid == 0) atomicAdd(&g_sync[2 + (t0 >> 7)], 1);
        }
    }

    // ---- phase 2: tag consumers (work-steal 64 chunks of 128 tokens) ----
    {
        float* tsw = dynsm;            // [256][64] transposed tagW
        float* tsb = dynsm + TAG_SW;   // [64]
        __syncthreads();
        for (int i = tid; i < TAG_SW; i += 256) tsw[i] = 0.f;
        if (tid < 64) tsb[tid] = (tid < TAGS) ? tagb[tid] : 0.f;
        __syncthreads();
        for (int i = tid; i < TAGS * 256; i += 256) {
            int tg = i >> 8, k = i & 255;
            tsw[k * 64 + tg] = tagW[i];
        }
        __syncthreads();

        const int lane = tid & 31, warp = tid >> 5;
        const bool v1 = (32 + lane) < TAGS;

        for (;;) {
            if (tid == 0) s_u = atomicAdd(&g_sync[1], 1);
            __syncthreads();
            const int ck = s_u;
            if (ck >= 64) break;
            wait_ge_sleep(&g_sync[66 + ck], 8);

            #pragma unroll 1
            for (int it = 0; it < 16; it++) {
                const int token = ck * 128 + it * 8 + warp;
                const float4* hp4 = (const float4*)(g_wh + (size_t)token * 256);

                float a0 = 0.f, a1 = 0.f;
                #pragma unroll 8
                for (int k4 = 0; k4 < 64; k4++) {
                    float4 h = hp4[k4];
                    const float* p = tsw + k4 * 256 + lane;
                    a0 = fmaf(h.x, p[0],   a0);  a1 = fmaf(h.x, p[32],  a1);
                    a0 = fmaf(h.y, p[64],  a0);  a1 = fmaf(h.y, p[96],  a1);
                    a0 = fmaf(h.z, p[128], a0);  a1 = fmaf(h.z, p[160], a1);
                    a0 = fmaf(h.w, p[192], a0);  a1 = fmaf(h.w, p[224], a1);
                }
                a0 += tsb[lane];
                a1 += tsb[32 + lane];

                float mx = fmaxf(a0, v1 ? a1 : -3.4e38f);
                #pragma unroll
                for (int off = 16; off; off >>= 1)
                    mx = fmaxf(mx, __shfl_xor_sync(0xFFFFFFFFu, mx, off));
                float e = __expf(a0 - mx) + (v1 ? __expf(a1 - mx) : 0.f);
                #pragma unroll
                for (int off = 16; off; off >>= 1)
                    e += __shfl_xor_sync(0xFFFFFFFFu, e, off);
                float ls = __logf(e);

                out[(size_t)token * TAGS + lane] = a0 - mx - ls;
                if (v1) out[(size_t)token * TAGS + 32 + lane] = a1 - mx - ls;
            }
        }
    }
}

// =====================================================================
extern "C" void kernel_launch(void* const* d_in, const int* in_sizes, int n_in,
                              void* d_out, int out_size)
{
    const int*   word_idxs = (const int*)d_in[0];
    const int*   char_idxs = (const int*)d_in[1];
    const int*   char_lens = (const int*)d_in[2];
    const float* char_emb  = (const float*)d_in[3];
    const float* char_Wih  = (const float*)d_in[4];
    const float* char_Whh  = (const float*)d_in[5];
    const float* char_bih  = (const float*)d_in[6];
    const float* char_bhh  = (const float*)d_in[7];
    const float* word_emb  = (const float*)d_in[8];
    const float* word_Wih  = (const float*)d_in[9];
    const float* word_Whh  = (const float*)d_in[10];
    const float* word_bih  = (const float*)d_in[11];
    const float* word_bhh  = (const float*)d_in[12];
    const float* tag_W     = (const float*)d_in[13];
    const float* tag_b     = (const float*)d_in[14];
    float* out = (float*)d_out;

    void* sync_addr = nullptr;
    cudaGetSymbolAddress(&sync_addr, g_sync);
    cudaMemsetAsync(sync_addr, 0, sizeof(int) * 256);

    cudaFuncSetAttribute(mega_kernel,
                         cudaFuncAttributeMaxDynamicSharedMemorySize, MEGA_DYN_BYTES);

    mega_kernel<<<136, 256, MEGA_DYN_BYTES>>>(
        word_Whh, word_idxs, word_emb, word_Wih, word_bih, word_bhh,
        tag_W, tag_b,
        char_idxs, char_lens, char_emb, char_Wih, char_Whh, char_bih, char_bhh,
        out);
}